// round 1
// baseline (speedup 1.0000x reference)
#include <cuda_runtime.h>

// Transposed conv (full conv), B=8, H=W=256, CIN=COUT=64, 3x3, fp32 NHWC.
// out[b,p,q,co] = sum_{di,dj,ci} in[b,p-di,q-dj,ci] * ker[ci,co,di,dj]
// Direct conv over zero-padded input. SIMT fp32 with packed fma.rn.f32x2.

#define BB   8
#define HH   256
#define WW   256
#define CCH  64     // channels (cin == cout)
#define OH   258
#define OW   258
#define CIC  8      // ci chunk staged in smem
#define TP   8      // output rows per block
#define TQ   64     // output cols per block
#define NTHR 256

__global__ __launch_bounds__(NTHR, 1)
void tconv_f32x2_kernel(const float* __restrict__ gin,
                        const float* __restrict__ gw,
                        float* __restrict__ gout)
{
    // smem: input tile [ci][row][col] (col-contiguous for conflict-free LDS),
    //       weights [k=di*3+dj][ci][co] (warp-broadcast reads)
    __shared__ float s_in[CIC][10][68];      // 10 rows, 66 used cols (+pad)
    __shared__ float s_w[9][CIC][CCH];

    const int t  = threadIdx.x;
    const int bq = blockIdx.x, bp = blockIdx.y, b = blockIdx.z;
    const int p0 = bp * TP;
    const int q0 = bq * TQ;

    // thread decode: lane&1 -> co half, (lane>>1)&15 -> q group of 4, warp -> row
    const int coh = t & 1;
    const int co0 = coh * 32;
    const int tqb = ((t >> 1) & 15) * 4;
    const int tp  = t >> 5;

    // 16 float2 co-pairs x 4 pixels, packed as f32x2 in 64-bit regs
    unsigned long long acc[16][4];
#pragma unroll
    for (int i = 0; i < 16; i++)
#pragma unroll
        for (int j = 0; j < 4; j++) acc[i][j] = 0ull;

    const int i0 = p0 - 2;
    const int j0 = q0 - 2;

    for (int c0 = 0; c0 < CCH; c0 += CIC) {
        __syncthreads();

        // ---- stage input chunk: rows i0..i0+9, cols j0..j0+65, ci c0..c0+7 ----
        // one float4 over ci per item; zero-fill out-of-range
        for (int idx = t; idx < 10 * 66 * (CIC / 4); idx += NTHR) {
            int f4  = idx % (CIC / 4);
            int rem = idx / (CIC / 4);
            int jj  = rem % 66;
            int ii  = rem / 66;
            int gi = i0 + ii, gj = j0 + jj;
            float4 v = make_float4(0.f, 0.f, 0.f, 0.f);
            if (gi >= 0 && gi < HH && gj >= 0 && gj < WW) {
                v = *(const float4*)&gin[(((size_t)b * HH + gi) * WW + gj) * CCH + c0 + f4 * 4];
            }
            s_in[f4 * 4 + 0][ii][jj] = v.x;
            s_in[f4 * 4 + 1][ii][jj] = v.y;
            s_in[f4 * 4 + 2][ii][jj] = v.z;
            s_in[f4 * 4 + 3][ii][jj] = v.w;
        }

        // ---- stage weight chunk: s_w[k][ci][co] = gw[((c0+ci)*64+co)*9 + k] ----
        for (int e = t; e < 9 * CIC * CCH; e += NTHR) {
            int co = e % CCH;
            int ci = (e / CCH) % CIC;
            int k  = e / (CCH * CIC);
            s_w[k][ci][co] = gw[((size_t)(c0 + ci) * CCH + co) * 9 + k];
        }
        __syncthreads();

        // ---- compute ----
#pragma unroll 2
        for (int ci = 0; ci < CIC; ci++) {
            // 3x6 input window for this thread's 4 pixels, broadcast-packed f32x2
            unsigned long long iv2[3][6];
#pragma unroll
            for (int rr = 0; rr < 3; rr++) {
#pragma unroll
                for (int cc = 0; cc < 6; cc++) {
                    unsigned int u = __float_as_uint(s_in[ci][tp + rr][tqb + cc]);
                    iv2[rr][cc] = ((unsigned long long)u << 32) | (unsigned long long)u;
                }
            }
#pragma unroll
            for (int k = 0; k < 9; k++) {
                const int di = k / 3, dj = k % 3;
                const unsigned long long* w2 =
                    (const unsigned long long*)&s_w[k][ci][co0];
#pragma unroll
                for (int c2 = 0; c2 < 16; c2++) {
                    unsigned long long w = w2[c2];
#pragma unroll
                    for (int px = 0; px < 4; px++) {
                        asm("fma.rn.f32x2 %0, %1, %2, %0;"
                            : "+l"(acc[c2][px])
                            : "l"(iv2[2 - di][px + 2 - dj]), "l"(w));
                    }
                }
            }
        }
    }

    // ---- store ----
    const int p = p0 + tp;
#pragma unroll
    for (int px = 0; px < 4; px++) {
        int q = q0 + tqb + px;
        if (p < OH && q < OW) {
            float2* o = (float2*)&gout[(((size_t)b * OH + p) * OW + q) * CCH + co0];
#pragma unroll
            for (int c2 = 0; c2 < 16; c2++) {
                o[c2] = *(float2*)&acc[c2][px];
            }
        }
    }
}

extern "C" void kernel_launch(void* const* d_in, const int* in_sizes, int n_in,
                              void* d_out, int out_size)
{
    const float* gin = (const float*)d_in[0];   // [8,256,256,64] f32
    const float* gw  = (const float*)d_in[1];   // [64,64,3,3]    f32
    float* gout = (float*)d_out;                // [8,258,258,64] f32

    dim3 grid((OW + TQ - 1) / TQ,   // 5
              (OH + TP - 1) / TP,   // 33
              BB);                  // 8
    tconv_f32x2_kernel<<<grid, NTHR>>>(gin, gw, gout);
}

// round 3
// speedup vs baseline: 2.1023x; 2.1023x over previous
#include <cuda_runtime.h>
#include <cuda_bf16.h>
#include <cstdint>

// Transposed conv (full conv): B=8, H=W=256, CIN=COUT=64, 3x3, fp32 NHWC.
// out[b,p,q,co] = sum_{di,dj,ci} in[b,p-di,q-dj,ci] * ker[ci,co,di,dj]
// Warp-level mma.sync bf16 implicit GEMM (non-'a' PTX, works at compute_103),
// 2-term bf16 split: 3 products hi*hi + lo*hi + hi*lo, fp32 accum in regs.

#define IH 256
#define IW 256
#define NCH 64
#define OH 258
#define OW 258

// smem layout (dynamic)
#define B_TAP 16384                  // per tap: hi[64x128B] + lo[64x128B]
#define SM_B 0
#define SM_A (9 * B_TAP)             // 147456
#define A_TERM 8704                  // 68 px rows * 128B
#define A_SLOT (2 * A_TERM)          // hi + lo
#define SM_TOTAL (SM_A + 3 * A_SLOT) // 199680

#define NSTRIP 32                    // 8 b * 4 q-strips of 64
#define NWORK (NSTRIP * OH)          // 8256 row-units
#define NCTA 152

__device__ __forceinline__ uint32_t smem_u32(const void* p) {
    uint32_t a;
    asm("{ .reg .u64 t; cvta.to.shared.u64 t, %1; cvt.u32.u64 %0, t; }" : "=r"(a) : "l"(p));
    return a;
}

__device__ __forceinline__ void ldm4(uint32_t* r, uint32_t a) {
    asm volatile("ldmatrix.sync.aligned.m8n8.x4.shared.b16 {%0,%1,%2,%3}, [%4];"
                 : "=r"(r[0]), "=r"(r[1]), "=r"(r[2]), "=r"(r[3]) : "r"(a));
}

__device__ __forceinline__ void mma16816(float* c, const uint32_t* a,
                                         uint32_t b0, uint32_t b1) {
    asm volatile(
        "mma.sync.aligned.m16n8k16.row.col.f32.bf16.bf16.f32 "
        "{%0,%1,%2,%3}, {%4,%5,%6,%7}, {%8,%9}, {%0,%1,%2,%3};"
        : "+f"(c[0]), "+f"(c[1]), "+f"(c[2]), "+f"(c[3])
        : "r"(a[0]), "r"(a[1]), "r"(a[2]), "r"(a[3]), "r"(b0), "r"(b1));
}

// split x into bf16 hi + bf16 lo (residual), return raw 16-bit patterns
__device__ __forceinline__ void bsplit(float x, uint32_t& h, uint32_t& l) {
    __nv_bfloat16 hb = __float2bfloat16_rn(x);
    float r = x - __bfloat162float(hb);
    __nv_bfloat16 lb = __float2bfloat16_rn(r);
    h = (uint32_t)__bfloat16_as_ushort(hb);
    l = (uint32_t)__bfloat16_as_ushort(lb);
}

__device__ __forceinline__ void convert_row(char* smc, int b, int qg0, int r,
                                            const float* __restrict__ gin) {
    const int slot = r % 3;
    char* hi = smc + SM_A + slot * A_SLOT;
    char* lo = hi + A_TERM;
    const float* src = gin + (((size_t)b * IH + r) * IW) * NCH;
    for (int idx = threadIdx.x; idx < 68 * 16; idx += 256) {
        int j = idx >> 4, c4 = idx & 15;
        int c = qg0 - 2 + j;
        float4 v = make_float4(0.f, 0.f, 0.f, 0.f);
        if (c >= 0 && c < IW)
            v = __ldg((const float4*)(src + (size_t)c * NCH + c4 * 4));
        uint32_t h0, h1, h2, h3, l0, l1, l2, l3;
        bsplit(v.x, h0, l0); bsplit(v.y, h1, l1);
        bsplit(v.z, h2, l2); bsplit(v.w, h3, l3);
        uint2 hv = make_uint2(h0 | (h1 << 16), h2 | (h3 << 16));
        uint2 lv = make_uint2(l0 | (l1 << 16), l2 | (l3 << 16));
        uint32_t off = (uint32_t)j * 128 + (uint32_t)c4 * 8;
        uint32_t sw = off ^ ((off >> 3) & 0x70);
        *(uint2*)(hi + sw) = hv;
        *(uint2*)(lo + sw) = lv;
    }
}

__global__ void __launch_bounds__(256, 1)
tconv_mma_kernel(const float* __restrict__ gin, const float* __restrict__ gw,
                 float* __restrict__ gout)
{
    extern __shared__ char smem[];
    const uint32_t sb = smem_u32(smem);
    const int tid = threadIdx.x;
    const int lane = tid & 31;
    const int wid = tid >> 5;
    const int warp_m = wid & 3;   // 16-px group
    const int warp_n = wid >> 2;  // 32-co group

    // ---- B convert: gw[ci][co][tap] fp32 -> smem W^T[co][ci] bf16 hi/lo per tap ----
    for (int e = tid; e < NCH * NCH; e += 256) {
        int co = e & 63;
        int ci = e >> 6;
        const float* wp = gw + (size_t)e * 9;
        uint32_t off = (uint32_t)co * 128 + (uint32_t)ci * 2;
        uint32_t sw = off ^ ((off >> 3) & 0x70);
#pragma unroll
        for (int tap = 0; tap < 9; tap++) {
            uint32_t h, l;
            bsplit(wp[tap], h, l);
            *(unsigned short*)(smem + SM_B + tap * B_TAP + sw) = (unsigned short)h;
            *(unsigned short*)(smem + SM_B + tap * B_TAP + 8192 + sw) = (unsigned short)l;
        }
    }

    // ldmatrix lane maps
    const int lm = (lane & 7) + ((lane >> 3) & 1) * 8;   // row within 16
    const uint32_t kcl = (uint32_t)((lane >> 4) & 1) * 16;
    const int nl0 = warp_n * 32 + lm;
    const int nl1 = nl0 + 16;
    const uint32_t brow0 = (uint32_t)nl0 * 128, bm0 = (uint32_t)(nl0 & 7) << 4;
    const uint32_t brow1 = (uint32_t)nl1 * 128, bm1 = (uint32_t)(nl1 & 7) << 4;

    const int chunk = (NWORK + NCTA - 1) / NCTA;   // 55
    int u0 = blockIdx.x * chunk;
    int u1 = u0 + chunk; if (u1 > NWORK) u1 = NWORK;
    int cur_strip = -1;

    for (int u = u0; u < u1; u++) {
        const int strip = u / OH;
        const int p = u - strip * OH;
        const int b = strip >> 2;
        const int qg0 = (strip & 3) * 64;

        __syncthreads();   // previous compute done before ring overwrite
        if (strip != cur_strip) {
            if (p >= 2 && p - 2 < IH) convert_row(smem, b, qg0, p - 2, gin);
            if (p >= 1 && p - 1 < IH) convert_row(smem, b, qg0, p - 1, gin);
            cur_strip = strip;
        }
        if (p < IH) convert_row(smem, b, qg0, p, gin);
        __syncthreads();

        // ---- compute: C[16px x 32co] per warp ----
        float c[4][4];
#pragma unroll
        for (int i = 0; i < 4; i++)
#pragma unroll
            for (int j = 0; j < 4; j++) c[i][j] = 0.f;

#pragma unroll
        for (int di = 0; di < 3; di++) {
            const int r = p - di;
            if (r < 0 || r >= IH) continue;
            const int slot = r % 3;
            const uint32_t aBase = sb + SM_A + (uint32_t)slot * A_SLOT;
#pragma unroll
            for (int dj = 0; dj < 3; dj++) {
                const int tap = di * 3 + dj;
                const int rowi = warp_m * 16 + lm + 2 - dj;
                const uint32_t aX = aBase + (uint32_t)rowi * 128;
                const uint32_t am = (uint32_t)(rowi & 7) << 4;
                const uint32_t bb = sb + SM_B + (uint32_t)tap * B_TAP;
#pragma unroll
                for (int s = 0; s < 4; s++) {
                    const uint32_t kx = (uint32_t)s * 32 + kcl;
                    uint32_t Ah[4], Al[4], Bh0[4], Bh1[4], Bl0[4], Bl1[4];
                    const uint32_t ax = kx ^ am;
                    ldm4(Ah, aX + ax);
                    ldm4(Al, aX + ax + A_TERM);
                    const uint32_t b0 = bb + brow0 + (kx ^ bm0);
                    const uint32_t b1 = bb + brow1 + (kx ^ bm1);
                    ldm4(Bh0, b0);
                    ldm4(Bh1, b1);
                    ldm4(Bl0, b0 + 8192);
                    ldm4(Bl1, b1 + 8192);
                    // term 1: Ah * Bh
                    mma16816(c[0], Ah, Bh0[0], Bh0[2]);
                    mma16816(c[1], Ah, Bh0[1], Bh0[3]);
                    mma16816(c[2], Ah, Bh1[0], Bh1[2]);
                    mma16816(c[3], Ah, Bh1[1], Bh1[3]);
                    // term 2: Al * Bh
                    mma16816(c[0], Al, Bh0[0], Bh0[2]);
                    mma16816(c[1], Al, Bh0[1], Bh0[3]);
                    mma16816(c[2], Al, Bh1[0], Bh1[2]);
                    mma16816(c[3], Al, Bh1[1], Bh1[3]);
                    // term 3: Ah * Bl
                    mma16816(c[0], Ah, Bl0[0], Bl0[2]);
                    mma16816(c[1], Ah, Bl0[1], Bl0[3]);
                    mma16816(c[2], Ah, Bl1[0], Bl1[2]);
                    mma16816(c[3], Ah, Bl1[1], Bl1[3]);
                }
            }
        }

        // ---- store: D layout m = t/4 (+8), n = 2*(t%4) ----
        const int q = qg0 + warp_m * 16 + (lane >> 2);
        float* orow = gout + (((size_t)b * OH + p) * OW + q) * NCH;
#pragma unroll
        for (int nt = 0; nt < 4; nt++) {
            const int co = warp_n * 32 + nt * 8 + (lane & 3) * 2;
            *(float2*)(orow + co) = make_float2(c[nt][0], c[nt][1]);
            *(float2*)(orow + 8 * NCH + co) = make_float2(c[nt][2], c[nt][3]);
        }
    }
}

// ---- tail: output columns q = 256, 257 (exact fp32 SIMT, tiny) ----
__global__ void tconv_tail_kernel(const float* __restrict__ gin,
                                  const float* __restrict__ gw,
                                  float* __restrict__ gout)
{
    const int p = blockIdx.x;
    const int b = blockIdx.y;
    const int q = 256 + (threadIdx.x >> 6);
    const int co = threadIdx.x & 63;

    float acc = 0.f;
#pragma unroll
    for (int di = 0; di < 3; di++) {
        int r = p - di;
        if (r < 0 || r >= IH) continue;
#pragma unroll
        for (int dj = 0; dj < 3; dj++) {
            int cc = q - dj;
            if (cc >= IW) continue;
            const float* ip = gin + (((size_t)b * IH + r) * IW + cc) * NCH;
            const float* wp = gw + (size_t)(di * 3 + dj) + (size_t)co * 9;
#pragma unroll 16
            for (int ci = 0; ci < NCH; ci++)
                acc = fmaf(ip[ci], wp[(size_t)ci * NCH * 9], acc);
        }
    }
    gout[(((size_t)b * OH + p) * OW + q) * NCH + co] = acc;
}

extern "C" void kernel_launch(void* const* d_in, const int* in_sizes, int n_in,
                              void* d_out, int out_size)
{
    const float* gin = (const float*)d_in[0]; // [8,256,256,64]
    const float* gw  = (const float*)d_in[1]; // [64,64,3,3]
    float* gout = (float*)d_out;              // [8,258,258,64]

    cudaFuncSetAttribute(tconv_mma_kernel,
                         cudaFuncAttributeMaxDynamicSharedMemorySize, SM_TOTAL);
    tconv_mma_kernel<<<NCTA, 256, SM_TOTAL>>>(gin, gw, gout);
    tconv_tail_kernel<<<dim3(OH, 8), 128>>>(gin, gw, gout);
}

// round 4
// speedup vs baseline: 2.2670x; 1.0783x over previous
#include <cuda_runtime.h>
#include <cuda_fp16.h>
#include <cstdint>

// Transposed conv (full conv): B=8, H=W=256, CIN=COUT=64, 3x3, fp32 NHWC.
// out[b,p,q,co] = sum_{di,dj,ci} in[b,p-di,q-dj,ci] * ker[ci,co,di,dj]
// mma.sync fp16 implicit GEMM. Weights split hi/lo fp16 (2 products:
// A*Wh + A*Wl), inputs single fp16, fp32 accumulate in registers.
// Each warp computes 2 output rows per B-fragment load.

#define IH 256
#define IW 256
#define NCH 64
#define OH 258
#define OW 258

// smem layout
#define B_TAP 16384                   // per tap: hi[64x128B] + lo[64x128B]
#define SM_B 0
#define SM_A (9 * B_TAP)              // 147456
#define A_SLOT 8704                   // 68 px rows * 128B (fp16, single term)
#define SM_TOTAL (SM_A + 4 * A_SLOT)  // 182272

#define NSTRIP 32                     // 8 b * 4 q-strips of 64
#define NPP 129                       // row pairs per strip (258/2)
#define NUNIT (NSTRIP * NPP)          // 4128
#define NCTA 152

__device__ __forceinline__ uint32_t smem_u32(const void* p) {
    uint32_t a;
    asm("{ .reg .u64 t; cvta.to.shared.u64 t, %1; cvt.u32.u64 %0, t; }" : "=r"(a) : "l"(p));
    return a;
}

__device__ __forceinline__ void ldm4(uint32_t* r, uint32_t a) {
    asm volatile("ldmatrix.sync.aligned.m8n8.x4.shared.b16 {%0,%1,%2,%3}, [%4];"
                 : "=r"(r[0]), "=r"(r[1]), "=r"(r[2]), "=r"(r[3]) : "r"(a));
}

__device__ __forceinline__ void mma16816(float* c, const uint32_t* a,
                                         uint32_t b0, uint32_t b1) {
    asm volatile(
        "mma.sync.aligned.m16n8k16.row.col.f32.f16.f16.f32 "
        "{%0,%1,%2,%3}, {%4,%5,%6,%7}, {%8,%9}, {%0,%1,%2,%3};"
        : "+f"(c[0]), "+f"(c[1]), "+f"(c[2]), "+f"(c[3])
        : "r"(a[0]), "r"(a[1]), "r"(a[2]), "r"(a[3]), "r"(b0), "r"(b1));
}

// split x into fp16 hi + fp16 lo (residual)
__device__ __forceinline__ void hsplit(float x, uint32_t& h, uint32_t& l) {
    __half hb = __float2half_rn(x);
    float r = x - __half2float(hb);
    __half lb = __float2half_rn(r);
    h = (uint32_t)__half_as_ushort(hb);
    l = (uint32_t)__half_as_ushort(lb);
}

// convert one input row (fp32 -> fp16) into ring slot r & 3
__device__ __forceinline__ void convert_row(char* smc, int b, int qg0, int r,
                                            const float* __restrict__ gin) {
    char* dst = smc + SM_A + (r & 3) * A_SLOT;
    const float* src = gin + (((size_t)b * IH + r) * IW) * NCH;
    for (int idx = threadIdx.x; idx < 68 * 16; idx += 256) {
        int j = idx >> 4, c4 = idx & 15;
        int c = qg0 - 2 + j;
        float4 v = make_float4(0.f, 0.f, 0.f, 0.f);
        if (c >= 0 && c < IW)
            v = __ldg((const float4*)(src + (size_t)c * NCH + c4 * 4));
        __half2 h01 = make_half2(__float2half_rn(v.x), __float2half_rn(v.y));
        __half2 h23 = make_half2(__float2half_rn(v.z), __float2half_rn(v.w));
        uint32_t off = (uint32_t)j * 128 + (uint32_t)c4 * 8;
        uint32_t sw = off ^ ((off >> 3) & 0x70);
        *(uint2*)(dst + sw) = make_uint2(*(uint32_t*)&h01, *(uint32_t*)&h23);
    }
}

__global__ void __launch_bounds__(256, 1)
tconv_mma_kernel(const float* __restrict__ gin, const float* __restrict__ gw,
                 float* __restrict__ gout)
{
    extern __shared__ char smem[];
    const uint32_t sb = smem_u32(smem);
    const int tid = threadIdx.x;
    const int lane = tid & 31;
    const int wid = tid >> 5;
    const int warp_m = wid & 3;   // 16-px group
    const int warp_n = wid >> 2;  // 32-co group

    // ---- weight convert: gw[ci][co][tap] -> smem W^T[co][ci] fp16 hi/lo ----
    for (int e = tid; e < NCH * NCH; e += 256) {
        int ci = e >> 6, co = e & 63;
        const float* wp = gw + (size_t)e * 9;
        uint32_t off = (uint32_t)co * 128 + (uint32_t)ci * 2;
        uint32_t sw = off ^ ((off >> 3) & 0x70);
#pragma unroll
        for (int tap = 0; tap < 9; tap++) {
            uint32_t h, l;
            hsplit(wp[tap], h, l);
            *(unsigned short*)(smem + SM_B + tap * B_TAP + sw) = (unsigned short)h;
            *(unsigned short*)(smem + SM_B + tap * B_TAP + 8192 + sw) = (unsigned short)l;
        }
    }

    // ldmatrix lane maps
    const int lm = (lane & 7) + ((lane >> 3) & 1) * 8;
    const uint32_t kcl = (uint32_t)((lane >> 4) & 1) * 16;
    const int nl0 = warp_n * 32 + lm;
    const int nl1 = nl0 + 16;
    const uint32_t brow0 = (uint32_t)nl0 * 128, bm0 = (uint32_t)(nl0 & 7) << 4;
    const uint32_t brow1 = (uint32_t)nl1 * 128, bm1 = (uint32_t)(nl1 & 7) << 4;

    const int chunk = (NUNIT + NCTA - 1) / NCTA;   // 28
    int u0 = blockIdx.x * chunk;
    int u1 = u0 + chunk; if (u1 > NUNIT) u1 = NUNIT;
    int cur_strip = -1;

    for (int u = u0; u < u1; u++) {
        const int strip = u / NPP;
        const int pp = u - strip * NPP;
        const int p0 = pp * 2;
        const int b = strip >> 2;
        const int qg0 = (strip & 3) * 64;

        __syncthreads();   // previous compute done before ring overwrite
        if (strip != cur_strip) {
            if (p0 - 2 >= 0 && p0 - 2 < IH) convert_row(smem, b, qg0, p0 - 2, gin);
            if (p0 - 1 >= 0 && p0 - 1 < IH) convert_row(smem, b, qg0, p0 - 1, gin);
            cur_strip = strip;
        }
        if (p0 < IH) convert_row(smem, b, qg0, p0, gin);
        if (p0 + 1 < IH) convert_row(smem, b, qg0, p0 + 1, gin);
        __syncthreads();

        // ---- compute: per warp, rows {p0, p0+1}, 16px x 32co each ----
        float c[2][4][4];
#pragma unroll
        for (int rr = 0; rr < 2; rr++)
#pragma unroll
            for (int i = 0; i < 4; i++)
#pragma unroll
                for (int j = 0; j < 4; j++) c[rr][i][j] = 0.f;

#pragma unroll
        for (int di = 0; di < 3; di++) {
            const int r0 = p0 - di;
            const int r1 = r0 + 1;
            const bool ok0 = (r0 >= 0 && r0 < IH);
            const bool ok1 = (r1 >= 0 && r1 < IH);
            if (!ok0 && !ok1) continue;
            const uint32_t a0Base = sb + SM_A + (uint32_t)(r0 & 3) * A_SLOT;
            const uint32_t a1Base = sb + SM_A + (uint32_t)(r1 & 3) * A_SLOT;
#pragma unroll
            for (int dj = 0; dj < 3; dj++) {
                const int tap = di * 3 + dj;
                const int rowi = warp_m * 16 + lm + 2 - dj;
                const uint32_t arow = (uint32_t)rowi * 128;
                const uint32_t am = (uint32_t)(rowi & 7) << 4;
                const uint32_t bbh = sb + SM_B + (uint32_t)tap * B_TAP;
#pragma unroll
                for (int s = 0; s < 4; s++) {
                    const uint32_t kx = (uint32_t)s * 32 + kcl;
                    uint32_t Bh0[4], Bh1[4], Bl0[4], Bl1[4];
                    const uint32_t bAddr0 = bbh + brow0 + (kx ^ bm0);
                    const uint32_t bAddr1 = bbh + brow1 + (kx ^ bm1);
                    ldm4(Bh0, bAddr0);
                    ldm4(Bh1, bAddr1);
                    ldm4(Bl0, bAddr0 + 8192);
                    ldm4(Bl1, bAddr1 + 8192);
                    const uint32_t ax = arow + (kx ^ am);
                    if (ok0) {
                        uint32_t A0[4];
                        ldm4(A0, a0Base + ax);
                        mma16816(c[0][0], A0, Bh0[0], Bh0[2]);
                        mma16816(c[0][1], A0, Bh0[1], Bh0[3]);
                        mma16816(c[0][2], A0, Bh1[0], Bh1[2]);
                        mma16816(c[0][3], A0, Bh1[1], Bh1[3]);
                        mma16816(c[0][0], A0, Bl0[0], Bl0[2]);
                        mma16816(c[0][1], A0, Bl0[1], Bl0[3]);
                        mma16816(c[0][2], A0, Bl1[0], Bl1[2]);
                        mma16816(c[0][3], A0, Bl1[1], Bl1[3]);
                    }
                    if (ok1) {
                        uint32_t A1[4];
                        ldm4(A1, a1Base + ax);
                        mma16816(c[1][0], A1, Bh0[0], Bh0[2]);
                        mma16816(c[1][1], A1, Bh0[1], Bh0[3]);
                        mma16816(c[1][2], A1, Bh1[0], Bh1[2]);
                        mma16816(c[1][3], A1, Bh1[1], Bh1[3]);
                        mma16816(c[1][0], A1, Bl0[0], Bl0[2]);
                        mma16816(c[1][1], A1, Bl0[1], Bl0[3]);
                        mma16816(c[1][2], A1, Bl1[0], Bl1[2]);
                        mma16816(c[1][3], A1, Bl1[1], Bl1[3]);
                    }
                }
            }
        }

        // ---- store both rows ----
        const int q = qg0 + warp_m * 16 + (lane >> 2);
#pragma unroll
        for (int rr = 0; rr < 2; rr++) {
            float* orow = gout + (((size_t)b * OH + (p0 + rr)) * OW + q) * NCH;
#pragma unroll
            for (int nt = 0; nt < 4; nt++) {
                const int co = warp_n * 32 + nt * 8 + (lane & 3) * 2;
                *(float2*)(orow + co) = make_float2(c[rr][nt][0], c[rr][nt][1]);
                *(float2*)(orow + 8 * NCH + co) = make_float2(c[rr][nt][2], c[rr][nt][3]);
            }
        }
    }
}

// ---- tail: output columns q = 256, 257 (exact fp32, smem-cached weights) ----
// only taps with dj >= 1 reach these columns: t6 = di*2 + (dj-1)
__global__ void tconv_tail_kernel(const float* __restrict__ gin,
                                  const float* __restrict__ gw,
                                  float* __restrict__ gout)
{
    __shared__ float w6[6][64][64];   // [t6][ci][co], 98304 bytes
    const int tid = threadIdx.x;
    const int b = blockIdx.y;
    const int p0 = blockIdx.x * 8;

    for (int idx = tid; idx < 6 * 64 * 64; idx += 128) {
        int co = idx & 63;
        int ci = (idx >> 6) & 63;
        int t6 = idx >> 12;
        int di = t6 >> 1, dj = (t6 & 1) + 1;
        w6[t6][ci][co] = gw[((size_t)ci * 64 + co) * 9 + di * 3 + dj];
    }
    __syncthreads();

    const int q = 256 + (tid >> 6);
    const int co = tid & 63;

    for (int pi = 0; pi < 8; pi++) {
        const int p = p0 + pi;
        if (p >= OH) break;
        float acc = 0.f;
#pragma unroll
        for (int di = 0; di < 3; di++) {
            const int r = p - di;
            if (r < 0 || r >= IH) continue;
#pragma unroll
            for (int dj = 1; dj < 3; dj++) {
                const int cc = q - dj;
                if (cc >= IW) continue;
                const int t6 = di * 2 + (dj - 1);
                const float* ip = gin + (((size_t)b * IH + r) * IW + cc) * NCH;
#pragma unroll 16
                for (int ci = 0; ci < NCH; ci++)
                    acc = fmaf(__ldg(ip + ci), w6[t6][ci][co], acc);
            }
        }
        gout[(((size_t)b * OH + p) * OW + q) * NCH + co] = acc;
    }
}

extern "C" void kernel_launch(void* const* d_in, const int* in_sizes, int n_in,
                              void* d_out, int out_size)
{
    const float* gin = (const float*)d_in[0]; // [8,256,256,64]
    const float* gw  = (const float*)d_in[1]; // [64,64,3,3]
    float* gout = (float*)d_out;              // [8,258,258,64]

    cudaFuncSetAttribute(tconv_mma_kernel,
                         cudaFuncAttributeMaxDynamicSharedMemorySize, SM_TOTAL);
    tconv_mma_kernel<<<NCTA, 256, SM_TOTAL>>>(gin, gw, gout);
    tconv_tail_kernel<<<dim3(33, 8), 128>>>(gin, gw, gout);
}

// round 5
// speedup vs baseline: 3.3448x; 1.4754x over previous
#include <cuda_runtime.h>
#include <cuda_fp16.h>
#include <cstdint>

// Transposed conv (full conv): B=8, H=W=256, CIN=COUT=64, 3x3, fp32 NHWC.
// out[b,p,q,co] = sum_{di,dj,ci} in[b,p-di,q-dj,ci] * ker[ci,co,di,dj]
// mma.sync fp16 implicit GEMM, single product (both operands fp16 RN),
// fp32 accumulate. 4 output rows per unit; tail columns (q=256,257) as
// packed 64-pixel MMA units inside the same persistent kernel.

#define IH 256
#define IW 256
#define NCH 64
#define OH 258
#define OW 258

// smem layout
#define B_TAP 8192                    // per tap: 64 co rows x 128B (fp16 K-major)
#define SM_B 0
#define SM_A (9 * B_TAP)              // 73728
#define A_SLOT 8704                   // 68 px rows * 128B
#define SM_TOTAL (SM_A + 8 * A_SLOT)  // 143360

#define NPB 65                        // 4-row blocks per strip (258 -> 65)
#define NSTRIP 32                     // 8 b * 4 q-strips of 64
#define NMAIN (NSTRIP * NPB)          // 2080
#define NTPX (8 * OH * 2)             // 4128 tail pixels
#define NTAIL 65                      // tail units (64 px each)
#define NCTA 152

__device__ __forceinline__ uint32_t smem_u32(const void* p) {
    uint32_t a;
    asm("{ .reg .u64 t; cvta.to.shared.u64 t, %1; cvt.u32.u64 %0, t; }" : "=r"(a) : "l"(p));
    return a;
}

__device__ __forceinline__ void ldm4(uint32_t* r, uint32_t a) {
    asm volatile("ldmatrix.sync.aligned.m8n8.x4.shared.b16 {%0,%1,%2,%3}, [%4];"
                 : "=r"(r[0]), "=r"(r[1]), "=r"(r[2]), "=r"(r[3]) : "r"(a));
}

__device__ __forceinline__ void mma16816(float* c, const uint32_t* a,
                                         uint32_t b0, uint32_t b1) {
    asm volatile(
        "mma.sync.aligned.m16n8k16.row.col.f32.f16.f16.f32 "
        "{%0,%1,%2,%3}, {%4,%5,%6,%7}, {%8,%9}, {%0,%1,%2,%3};"
        : "+f"(c[0]), "+f"(c[1]), "+f"(c[2]), "+f"(c[3])
        : "r"(a[0]), "r"(a[1]), "r"(a[2]), "r"(a[3]), "r"(b0), "r"(b1));
}

// convert one input row (fp32 -> fp16) into ring slot r & 7
__device__ __forceinline__ void convert_row(char* smc, int b, int qg0, int r,
                                            const float* __restrict__ gin) {
    char* dst = smc + SM_A + (r & 7) * A_SLOT;
    const float* src = gin + (((size_t)b * IH + r) * IW) * NCH;
    for (int idx = threadIdx.x; idx < 68 * 16; idx += 256) {
        int j = idx >> 4, c4 = idx & 15;
        int c = qg0 - 2 + j;
        float4 v = make_float4(0.f, 0.f, 0.f, 0.f);
        if (c >= 0 && c < IW)
            v = __ldg((const float4*)(src + (size_t)c * NCH + c4 * 4));
        __half2 h01 = make_half2(__float2half_rn(v.x), __float2half_rn(v.y));
        __half2 h23 = make_half2(__float2half_rn(v.z), __float2half_rn(v.w));
        uint32_t off = (uint32_t)j * 128 + (uint32_t)c4 * 8;
        uint32_t sw = off ^ ((off >> 3) & 0x70);
        *(uint2*)(dst + sw) = make_uint2(*(uint32_t*)&h01, *(uint32_t*)&h23);
    }
}

__global__ void __launch_bounds__(256, 1)
tconv_mma_kernel(const float* __restrict__ gin, const float* __restrict__ gw,
                 float* __restrict__ gout)
{
    extern __shared__ char smem[];
    const uint32_t sb = smem_u32(smem);
    const int tid = threadIdx.x;
    const int lane = tid & 31;
    const int wid = tid >> 5;
    const int warp_m = wid & 3;   // 16-px group
    const int warp_n = wid >> 2;  // 32-co group

    // ---- weight convert: gw[ci][co][tap] -> smem W^T[co][ci] fp16 ----
    for (int e = tid; e < NCH * NCH; e += 256) {
        int ci = e >> 6, co = e & 63;
        const float* wp = gw + (size_t)e * 9;
        uint32_t off = (uint32_t)co * 128 + (uint32_t)ci * 2;
        uint32_t sw = off ^ ((off >> 3) & 0x70);
#pragma unroll
        for (int tap = 0; tap < 9; tap++) {
            __half h = __float2half_rn(wp[tap]);
            *(unsigned short*)(smem + SM_B + tap * B_TAP + sw) = __half_as_ushort(h);
        }
    }

    // ldmatrix lane maps
    const int lm = (lane & 7) + ((lane >> 3) & 1) * 8;
    const uint32_t kcl = (uint32_t)((lane >> 4) & 1) * 16;
    const int nl0 = warp_n * 32 + lm;
    const int nl1 = nl0 + 16;
    const uint32_t brow0 = (uint32_t)nl0 * 128, bm0 = (uint32_t)(nl0 & 7) << 4;
    const uint32_t brow1 = (uint32_t)nl1 * 128, bm1 = (uint32_t)(nl1 & 7) << 4;

    // balanced contiguous chunks of main units
    const int u0 = (int)(((long long)blockIdx.x * NMAIN) / NCTA);
    const int u1 = (int)(((long long)(blockIdx.x + 1) * NMAIN) / NCTA);
    int cur_strip = -1;

    for (int u = u0; u < u1; u++) {
        const int strip = u / NPB;
        const int pb = u - strip * NPB;
        const int p0 = pb * 4;
        const int b = strip >> 2;
        const int qg0 = (strip & 3) * 64;

        __syncthreads();   // prev compute done before ring overwrite
        if (strip != cur_strip) {
            if (p0 - 2 >= 0 && p0 - 2 < IH) convert_row(smem, b, qg0, p0 - 2, gin);
            if (p0 - 1 >= 0 && p0 - 1 < IH) convert_row(smem, b, qg0, p0 - 1, gin);
            cur_strip = strip;
        }
#pragma unroll
        for (int rr = 0; rr < 4; rr++)
            if (p0 + rr < IH) convert_row(smem, b, qg0, p0 + rr, gin);
        __syncthreads();

        // ---- compute rows p0..p0+3, 16px x 32co per warp per row ----
        float c[4][4][4];
#pragma unroll
        for (int rr = 0; rr < 4; rr++)
#pragma unroll
            for (int i = 0; i < 4; i++)
#pragma unroll
                for (int j = 0; j < 4; j++) c[rr][i][j] = 0.f;

#pragma unroll
        for (int di = 0; di < 3; di++) {
#pragma unroll
            for (int dj = 0; dj < 3; dj++) {
                const int tap = di * 3 + dj;
                const int rowi = warp_m * 16 + lm + 2 - dj;
                const uint32_t arow = (uint32_t)rowi * 128;
                const uint32_t am = (uint32_t)(rowi & 7) << 4;
                const uint32_t bb = sb + SM_B + (uint32_t)tap * B_TAP;
#pragma unroll
                for (int s = 0; s < 4; s++) {
                    const uint32_t kx = (uint32_t)s * 32 + kcl;
                    uint32_t B0[4], B1[4];
                    ldm4(B0, bb + brow0 + (kx ^ bm0));
                    ldm4(B1, bb + brow1 + (kx ^ bm1));
                    const uint32_t ax = arow + (kx ^ am);
#pragma unroll
                    for (int rr = 0; rr < 4; rr++) {
                        const int rp = p0 + rr - di;
                        if (rp >= 0 && rp < IH) {
                            uint32_t A[4];
                            ldm4(A, sb + SM_A + (uint32_t)(rp & 7) * A_SLOT + ax);
                            mma16816(c[rr][0], A, B0[0], B0[2]);
                            mma16816(c[rr][1], A, B0[1], B0[3]);
                            mma16816(c[rr][2], A, B1[0], B1[2]);
                            mma16816(c[rr][3], A, B1[1], B1[3]);
                        }
                    }
                }
            }
        }

        // ---- store ----
        const int q = qg0 + warp_m * 16 + (lane >> 2);
#pragma unroll
        for (int rr = 0; rr < 4; rr++) {
            const int p = p0 + rr;
            if (p >= OH) break;
            float* orow = gout + (((size_t)b * OH + p) * OW + q) * NCH;
#pragma unroll
            for (int nt = 0; nt < 4; nt++) {
                const int co = warp_n * 32 + nt * 8 + (lane & 3) * 2;
                *(float2*)(orow + co) = make_float2(c[rr][nt][0], c[rr][nt][1]);
                *(float2*)(orow + 8 * NCH + co) = make_float2(c[rr][nt][2], c[rr][nt][3]);
            }
        }
    }

    // ================= tail units: q in {256,257}, 64 px per unit ============
    if (blockIdx.x < NTAIL) {
        const int t = blockIdx.x;
        const int g0 = t * 64;

        float ct[4][4];
#pragma unroll
        for (int i = 0; i < 4; i++)
#pragma unroll
            for (int j = 0; j < 4; j++) ct[i][j] = 0.f;

        const int rowi = warp_m * 16 + lm;
        const uint32_t arow = (uint32_t)rowi * 128;
        const uint32_t am = (uint32_t)(rowi & 7) << 4;

        for (int tap = 0; tap < 9; tap++) {
            const int di = tap / 3, dj = tap % 3;
            __syncthreads();   // prev tap's mma reads done (also first: ring reads done)
            // im2col gather into A slot 0: A[m][ci] = in[b][p-di][q-dj][ci]
            for (int idx = tid; idx < 64 * 16; idx += 256) {
                int m = idx >> 4, c4 = idx & 15;
                int g = g0 + m;
                int bb_ = g / (OH * 2);
                int rem = g - bb_ * (OH * 2);
                int p = rem >> 1;
                int qq = 256 + (rem & 1);
                int r = p - di, cc = qq - dj;
                float4 v = make_float4(0.f, 0.f, 0.f, 0.f);
                if (g < NTPX && r >= 0 && r < IH && cc < IW)
                    v = __ldg((const float4*)(gin +
                        ((((size_t)bb_ * IH + r) * IW + cc) * NCH) + c4 * 4));
                __half2 h01 = make_half2(__float2half_rn(v.x), __float2half_rn(v.y));
                __half2 h23 = make_half2(__float2half_rn(v.z), __float2half_rn(v.w));
                uint32_t off = (uint32_t)m * 128 + (uint32_t)c4 * 8;
                uint32_t sw = off ^ ((off >> 3) & 0x70);
                *(uint2*)(smem + SM_A + sw) = make_uint2(*(uint32_t*)&h01, *(uint32_t*)&h23);
            }
            __syncthreads();

            const uint32_t bb = sb + SM_B + (uint32_t)tap * B_TAP;
#pragma unroll
            for (int s = 0; s < 4; s++) {
                const uint32_t kx = (uint32_t)s * 32 + kcl;
                uint32_t B0[4], B1[4], A[4];
                ldm4(B0, bb + brow0 + (kx ^ bm0));
                ldm4(B1, bb + brow1 + (kx ^ bm1));
                ldm4(A, sb + SM_A + arow + (kx ^ am));
                mma16816(ct[0], A, B0[0], B0[2]);
                mma16816(ct[1], A, B0[1], B0[3]);
                mma16816(ct[2], A, B1[0], B1[2]);
                mma16816(ct[3], A, B1[1], B1[3]);
            }
        }

        // store tail
        const int m0 = warp_m * 16 + (lane >> 2);
#pragma unroll
        for (int half = 0; half < 2; half++) {
            const int g = g0 + m0 + half * 8;
            if (g < NTPX) {
                const int bb_ = g / (OH * 2);
                const int rem = g - bb_ * (OH * 2);
                const int p = rem >> 1;
                const int qq = 256 + (rem & 1);
                float* orow = gout + (((size_t)bb_ * OH + p) * OW + qq) * NCH;
#pragma unroll
                for (int nt = 0; nt < 4; nt++) {
                    const int co = warp_n * 32 + nt * 8 + (lane & 3) * 2;
                    *(float2*)(orow + co) =
                        make_float2(ct[nt][half * 2], ct[nt][half * 2 + 1]);
                }
            }
        }
    }
}

extern "C" void kernel_launch(void* const* d_in, const int* in_sizes, int n_in,
                              void* d_out, int out_size)
{
    const float* gin = (const float*)d_in[0]; // [8,256,256,64]
    const float* gw  = (const float*)d_in[1]; // [64,64,3,3]
    float* gout = (float*)d_out;              // [8,258,258,64]

    cudaFuncSetAttribute(tconv_mma_kernel,
                         cudaFuncAttributeMaxDynamicSharedMemorySize, SM_TOTAL);
    tconv_mma_kernel<<<NCTA, 256, SM_TOTAL>>>(gin, gw, gout);
}

// round 6
// speedup vs baseline: 4.8187x; 1.4407x over previous
#include <cuda_runtime.h>
#include <cuda_fp16.h>
#include <cstdint>

// Transposed conv (full conv): B=8, H=W=256, CIN=COUT=64, 3x3, fp32 NHWC.
// out[b,p,q,co] = sum_{di,dj,ci} in[b,p-di,q-dj,ci] * ker[ci,co,di,dj]
// mma.sync fp16 implicit GEMM, single product, fp32 accumulate.
// 512 threads (16 warps): warp grid 4(m) x 2(n) x 2(row-pair) over a
// 64px x 64co x 4row unit. Tail columns (q=256,257) as packed MMA units.

#define IH 256
#define IW 256
#define NCH 64
#define OH 258
#define OW 258

// smem layout
#define B_TAP 8192                    // per tap: 64 co rows x 128B (fp16 K-major)
#define SM_B 0
#define SM_A (9 * B_TAP)              // 73728
#define A_SLOT 8704                   // 68 px rows * 128B
#define SM_TOTAL (SM_A + 8 * A_SLOT)  // 143360

#define NPB 65                        // 4-row blocks per strip
#define NSTRIP 32                     // 8 b * 4 q-strips of 64
#define NMAIN (NSTRIP * NPB)          // 2080
#define NTPX (8 * OH * 2)             // 4128 tail pixels
#define NTAIL 65
#define NCTA 152
#define NTHR 512

__device__ __forceinline__ uint32_t smem_u32(const void* p) {
    uint32_t a;
    asm("{ .reg .u64 t; cvta.to.shared.u64 t, %1; cvt.u32.u64 %0, t; }" : "=r"(a) : "l"(p));
    return a;
}

__device__ __forceinline__ void ldm4(uint32_t* r, uint32_t a) {
    asm volatile("ldmatrix.sync.aligned.m8n8.x4.shared.b16 {%0,%1,%2,%3}, [%4];"
                 : "=r"(r[0]), "=r"(r[1]), "=r"(r[2]), "=r"(r[3]) : "r"(a));
}

__device__ __forceinline__ void mma16816(float* c, const uint32_t* a,
                                         uint32_t b0, uint32_t b1) {
    asm volatile(
        "mma.sync.aligned.m16n8k16.row.col.f32.f16.f16.f32 "
        "{%0,%1,%2,%3}, {%4,%5,%6,%7}, {%8,%9}, {%0,%1,%2,%3};"
        : "+f"(c[0]), "+f"(c[1]), "+f"(c[2]), "+f"(c[3])
        : "r"(a[0]), "r"(a[1]), "r"(a[2]), "r"(a[3]), "r"(b0), "r"(b1));
}

// convert one input row (fp32 -> fp16) into ring slot r & 7
__device__ __forceinline__ void convert_row(char* smc, int b, int qg0, int r,
                                            const float* __restrict__ gin) {
    char* dst = smc + SM_A + (r & 7) * A_SLOT;
    const float* src = gin + (((size_t)b * IH + r) * IW) * NCH;
    for (int idx = threadIdx.x; idx < 68 * 16; idx += NTHR) {
        int j = idx >> 4, c4 = idx & 15;
        int c = qg0 - 2 + j;
        float4 v = make_float4(0.f, 0.f, 0.f, 0.f);
        if (c >= 0 && c < IW)
            v = __ldg((const float4*)(src + (size_t)c * NCH + c4 * 4));
        __half2 h01 = make_half2(__float2half_rn(v.x), __float2half_rn(v.y));
        __half2 h23 = make_half2(__float2half_rn(v.z), __float2half_rn(v.w));
        uint32_t off = (uint32_t)j * 128 + (uint32_t)c4 * 8;
        uint32_t sw = off ^ ((off >> 3) & 0x70);
        *(uint2*)(dst + sw) = make_uint2(*(uint32_t*)&h01, *(uint32_t*)&h23);
    }
}

__global__ void __launch_bounds__(NTHR, 1)
tconv_mma_kernel(const float* __restrict__ gin, const float* __restrict__ gw,
                 float* __restrict__ gout)
{
    extern __shared__ char smem[];
    const uint32_t sb = smem_u32(smem);
    const int tid = threadIdx.x;
    const int lane = tid & 31;
    const int wid = tid >> 5;
    const int warp_m = wid & 3;          // 16-px group
    const int warp_n = (wid >> 2) & 1;   // 32-co group
    const int warp_r = wid >> 3;         // row-pair group

    // ---- weight convert: gw[ci][co][tap] -> smem W^T[co][ci] fp16 ----
    for (int e = tid; e < NCH * NCH; e += NTHR) {
        int ci = e >> 6, co = e & 63;
        const float* wp = gw + (size_t)e * 9;
        uint32_t off = (uint32_t)co * 128 + (uint32_t)ci * 2;
        uint32_t sw = off ^ ((off >> 3) & 0x70);
#pragma unroll
        for (int tap = 0; tap < 9; tap++) {
            __half h = __float2half_rn(wp[tap]);
            *(unsigned short*)(smem + SM_B + tap * B_TAP + sw) = __half_as_ushort(h);
        }
    }

    // ldmatrix lane maps
    const int lm = (lane & 7) + ((lane >> 3) & 1) * 8;
    const uint32_t kcl = (uint32_t)((lane >> 4) & 1) * 16;
    const int nl0 = warp_n * 32 + lm;
    const int nl1 = nl0 + 16;
    const uint32_t brow0 = (uint32_t)nl0 * 128, bm0 = (uint32_t)(nl0 & 7) << 4;
    const uint32_t brow1 = (uint32_t)nl1 * 128, bm1 = (uint32_t)(nl1 & 7) << 4;

    const int u0 = (int)(((long long)blockIdx.x * NMAIN) / NCTA);
    const int u1 = (int)(((long long)(blockIdx.x + 1) * NMAIN) / NCTA);
    int cur_strip = -1;

    for (int u = u0; u < u1; u++) {
        const int strip = u / NPB;
        const int pb = u - strip * NPB;
        const int p0 = pb * 4;
        const int b = strip >> 2;
        const int qg0 = (strip & 3) * 64;

        __syncthreads();   // prev compute done before ring overwrite
        if (strip != cur_strip) {
            if (p0 - 2 >= 0 && p0 - 2 < IH) convert_row(smem, b, qg0, p0 - 2, gin);
            if (p0 - 1 >= 0 && p0 - 1 < IH) convert_row(smem, b, qg0, p0 - 1, gin);
            cur_strip = strip;
        }
#pragma unroll
        for (int rr = 0; rr < 4; rr++)
            if (p0 + rr < IH) convert_row(smem, b, qg0, p0 + rr, gin);
        __syncthreads();

        // ---- compute: this warp's rows {pw, pw+1}, 16px x 32co each ----
        const int pw = p0 + warp_r * 2;
        float c[2][4][4];
#pragma unroll
        for (int rr = 0; rr < 2; rr++)
#pragma unroll
            for (int i = 0; i < 4; i++)
#pragma unroll
                for (int j = 0; j < 4; j++) c[rr][i][j] = 0.f;

#pragma unroll
        for (int di = 0; di < 3; di++) {
#pragma unroll
            for (int dj = 0; dj < 3; dj++) {
                const int tap = di * 3 + dj;
                const int rowi = warp_m * 16 + lm + 2 - dj;
                const uint32_t arow = (uint32_t)rowi * 128;
                const uint32_t am = (uint32_t)(rowi & 7) << 4;
                const uint32_t bb = sb + SM_B + (uint32_t)tap * B_TAP;
#pragma unroll
                for (int s = 0; s < 4; s++) {
                    const uint32_t kx = (uint32_t)s * 32 + kcl;
                    uint32_t B0[4], B1[4];
                    ldm4(B0, bb + brow0 + (kx ^ bm0));
                    ldm4(B1, bb + brow1 + (kx ^ bm1));
                    const uint32_t ax = arow + (kx ^ am);
#pragma unroll
                    for (int rr = 0; rr < 2; rr++) {
                        const int rp = pw + rr - di;
                        if (rp >= 0 && rp < IH) {
                            uint32_t A[4];
                            ldm4(A, sb + SM_A + (uint32_t)(rp & 7) * A_SLOT + ax);
                            mma16816(c[rr][0], A, B0[0], B0[2]);
                            mma16816(c[rr][1], A, B0[1], B0[3]);
                            mma16816(c[rr][2], A, B1[0], B1[2]);
                            mma16816(c[rr][3], A, B1[1], B1[3]);
                        }
                    }
                }
            }
        }

        // ---- store ----
        const int q = qg0 + warp_m * 16 + (lane >> 2);
#pragma unroll
        for (int rr = 0; rr < 2; rr++) {
            const int p = pw + rr;
            if (p >= OH) break;
            float* orow = gout + (((size_t)b * OH + p) * OW + q) * NCH;
#pragma unroll
            for (int nt = 0; nt < 4; nt++) {
                const int co = warp_n * 32 + nt * 8 + (lane & 3) * 2;
                *(float2*)(orow + co) = make_float2(c[rr][nt][0], c[rr][nt][1]);
                *(float2*)(orow + 8 * NCH + co) = make_float2(c[rr][nt][2], c[rr][nt][3]);
            }
        }
    }

    // ================= tail units: q in {256,257}, 64 px per unit ============
    if (blockIdx.x < NTAIL) {
        const int t = blockIdx.x;
        const int g0 = t * 64;

        float ct[4][4];
#pragma unroll
        for (int i = 0; i < 4; i++)
#pragma unroll
            for (int j = 0; j < 4; j++) ct[i][j] = 0.f;

        const int rowi = warp_m * 16 + lm;
        const uint32_t arow = (uint32_t)rowi * 128;
        const uint32_t am = (uint32_t)(rowi & 7) << 4;

        for (int tap = 0; tap < 9; tap++) {
            const int di = tap / 3, dj = tap % 3;
            __syncthreads();   // prev tap's mma reads done
            // im2col gather into A slot 0
            for (int idx = tid; idx < 64 * 16; idx += NTHR) {
                int m = idx >> 4, c4 = idx & 15;
                int g = g0 + m;
                int bb_ = g / (OH * 2);
                int rem = g - bb_ * (OH * 2);
                int p = rem >> 1;
                int qq = 256 + (rem & 1);
                int r = p - di, cc = qq - dj;
                float4 v = make_float4(0.f, 0.f, 0.f, 0.f);
                if (g < NTPX && r >= 0 && r < IH && cc < IW)
                    v = __ldg((const float4*)(gin +
                        ((((size_t)bb_ * IH + r) * IW + cc) * NCH) + c4 * 4));
                __half2 h01 = make_half2(__float2half_rn(v.x), __float2half_rn(v.y));
                __half2 h23 = make_half2(__float2half_rn(v.z), __float2half_rn(v.w));
                uint32_t off = (uint32_t)m * 128 + (uint32_t)c4 * 8;
                uint32_t sw = off ^ ((off >> 3) & 0x70);
                *(uint2*)(smem + SM_A + sw) = make_uint2(*(uint32_t*)&h01, *(uint32_t*)&h23);
            }
            __syncthreads();

            if (warp_r == 0) {
                const uint32_t bb = sb + SM_B + (uint32_t)tap * B_TAP;
#pragma unroll
                for (int s = 0; s < 4; s++) {
                    const uint32_t kx = (uint32_t)s * 32 + kcl;
                    uint32_t B0[4], B1[4], A[4];
                    ldm4(B0, bb + brow0 + (kx ^ bm0));
                    ldm4(B1, bb + brow1 + (kx ^ bm1));
                    ldm4(A, sb + SM_A + arow + (kx ^ am));
                    mma16816(ct[0], A, B0[0], B0[2]);
                    mma16816(ct[1], A, B0[1], B0[3]);
                    mma16816(ct[2], A, B1[0], B1[2]);
                    mma16816(ct[3], A, B1[1], B1[3]);
                }
            }
        }

        // store tail (warps 0-7 own the 64x64 tile)
        if (warp_r == 0) {
            const int m0 = warp_m * 16 + (lane >> 2);
#pragma unroll
            for (int half = 0; half < 2; half++) {
                const int g = g0 + m0 + half * 8;
                if (g < NTPX) {
                    const int bb_ = g / (OH * 2);
                    const int rem = g - bb_ * (OH * 2);
                    const int p = rem >> 1;
                    const int qq = 256 + (rem & 1);
                    float* orow = gout + (((size_t)bb_ * OH + p) * OW + qq) * NCH;
#pragma unroll
                    for (int nt = 0; nt < 4; nt++) {
                        const int co = warp_n * 32 + nt * 8 + (lane & 3) * 2;
                        *(float2*)(orow + co) =
                            make_float2(ct[nt][half * 2], ct[nt][half * 2 + 1]);
                    }
                }
            }
        }
    }
}

extern "C" void kernel_launch(void* const* d_in, const int* in_sizes, int n_in,
                              void* d_out, int out_size)
{
    const float* gin = (const float*)d_in[0]; // [8,256,256,64]
    const float* gw  = (const float*)d_in[1]; // [64,64,3,3]
    float* gout = (float*)d_out;              // [8,258,258,64]

    cudaFuncSetAttribute(tconv_mma_kernel,
                         cudaFuncAttributeMaxDynamicSharedMemorySize, SM_TOTAL);
    tconv_mma_kernel<<<NCTA, NTHR, SM_TOTAL>>>(gin, gw, gout);
}

// round 7
// speedup vs baseline: 5.1370x; 1.0661x over previous
#include <cuda_runtime.h>
#include <cuda_fp16.h>
#include <cstdint>

// Transposed conv (full conv): B=8, H=W=256, CIN=COUT=64, 3x3, fp32 NHWC.
// out[b,p,q,co] = sum_{di,dj,ci} in[b,p-di,q-dj,ci] * ker[ci,co,di,dj]
// mma.sync fp16 implicit GEMM, single product, fp32 accumulate.
// 1024 threads (32 warps): warp grid 4(m) x 2(n) x 4(row) over a
// 64px x 64co x 4row unit; 1 output row per warp for max latency hiding.

#define IH 256
#define IW 256
#define NCH 64
#define OH 258
#define OW 258

// smem layout
#define B_TAP 8192                    // per tap: 64 co rows x 128B (fp16 K-major)
#define SM_B 0
#define SM_A (9 * B_TAP)              // 73728
#define A_SLOT 8704                   // 68 px rows * 128B
#define SM_TOTAL (SM_A + 8 * A_SLOT)  // 143360

#define NPB 65                        // 4-row blocks per strip
#define NSTRIP 32                     // 8 b * 4 q-strips of 64
#define NMAIN (NSTRIP * NPB)          // 2080
#define NTPX (8 * OH * 2)             // 4128 tail pixels
#define NTAIL 65
#define NCTA 152
#define NTHR 1024

__device__ __forceinline__ uint32_t smem_u32(const void* p) {
    uint32_t a;
    asm("{ .reg .u64 t; cvta.to.shared.u64 t, %1; cvt.u32.u64 %0, t; }" : "=r"(a) : "l"(p));
    return a;
}

__device__ __forceinline__ void ldm4(uint32_t* r, uint32_t a) {
    asm volatile("ldmatrix.sync.aligned.m8n8.x4.shared.b16 {%0,%1,%2,%3}, [%4];"
                 : "=r"(r[0]), "=r"(r[1]), "=r"(r[2]), "=r"(r[3]) : "r"(a));
}

__device__ __forceinline__ void mma16816(float* c, const uint32_t* a,
                                         uint32_t b0, uint32_t b1) {
    asm volatile(
        "mma.sync.aligned.m16n8k16.row.col.f32.f16.f16.f32 "
        "{%0,%1,%2,%3}, {%4,%5,%6,%7}, {%8,%9}, {%0,%1,%2,%3};"
        : "+f"(c[0]), "+f"(c[1]), "+f"(c[2]), "+f"(c[3])
        : "r"(a[0]), "r"(a[1]), "r"(a[2]), "r"(a[3]), "r"(b0), "r"(b1));
}

// convert one input row (fp32 -> fp16) into ring slot r & 7
__device__ __forceinline__ void convert_row(char* smc, int b, int qg0, int r,
                                            const float* __restrict__ gin) {
    char* dst = smc + SM_A + (r & 7) * A_SLOT;
    const float* src = gin + (((size_t)b * IH + r) * IW) * NCH;
    for (int idx = threadIdx.x; idx < 68 * 16; idx += NTHR) {
        int j = idx >> 4, c4 = idx & 15;
        int c = qg0 - 2 + j;
        float4 v = make_float4(0.f, 0.f, 0.f, 0.f);
        if (c >= 0 && c < IW)
            v = __ldg((const float4*)(src + (size_t)c * NCH + c4 * 4));
        __half2 h01 = make_half2(__float2half_rn(v.x), __float2half_rn(v.y));
        __half2 h23 = make_half2(__float2half_rn(v.z), __float2half_rn(v.w));
        uint32_t off = (uint32_t)j * 128 + (uint32_t)c4 * 8;
        uint32_t sw = off ^ ((off >> 3) & 0x70);
        *(uint2*)(dst + sw) = make_uint2(*(uint32_t*)&h01, *(uint32_t*)&h23);
    }
}

__global__ void __launch_bounds__(NTHR, 1)
tconv_mma_kernel(const float* __restrict__ gin, const float* __restrict__ gw,
                 float* __restrict__ gout)
{
    extern __shared__ char smem[];
    const uint32_t sb = smem_u32(smem);
    const int tid = threadIdx.x;
    const int lane = tid & 31;
    const int wid = tid >> 5;
    const int warp_m = wid & 3;          // 16-px group
    const int warp_n = (wid >> 2) & 1;   // 32-co group
    const int warp_r = wid >> 3;         // row within 4-row block

    // ---- weight convert: gw[ci][co][tap] -> smem W^T[co][ci] fp16 ----
    for (int e = tid; e < NCH * NCH; e += NTHR) {
        int ci = e >> 6, co = e & 63;
        const float* wp = gw + (size_t)e * 9;
        uint32_t off = (uint32_t)co * 128 + (uint32_t)ci * 2;
        uint32_t sw = off ^ ((off >> 3) & 0x70);
#pragma unroll
        for (int tap = 0; tap < 9; tap++) {
            __half h = __float2half_rn(wp[tap]);
            *(unsigned short*)(smem + SM_B + tap * B_TAP + sw) = __half_as_ushort(h);
        }
    }

    // ldmatrix lane maps
    const int lm = (lane & 7) + ((lane >> 3) & 1) * 8;
    const uint32_t kcl = (uint32_t)((lane >> 4) & 1) * 16;
    const int nl0 = warp_n * 32 + lm;
    const int nl1 = nl0 + 16;
    const uint32_t brow0 = (uint32_t)nl0 * 128, bm0 = (uint32_t)(nl0 & 7) << 4;
    const uint32_t brow1 = (uint32_t)nl1 * 128, bm1 = (uint32_t)(nl1 & 7) << 4;

    const int u0 = (int)(((long long)blockIdx.x * NMAIN) / NCTA);
    const int u1 = (int)(((long long)(blockIdx.x + 1) * NMAIN) / NCTA);
    int cur_strip = -1;

    for (int u = u0; u < u1; u++) {
        const int strip = u / NPB;
        const int pb = u - strip * NPB;
        const int p0 = pb * 4;
        const int b = strip >> 2;
        const int qg0 = (strip & 3) * 64;

        __syncthreads();   // prev compute done before ring overwrite
        if (strip != cur_strip) {
            if (p0 - 2 >= 0 && p0 - 2 < IH) convert_row(smem, b, qg0, p0 - 2, gin);
            if (p0 - 1 >= 0 && p0 - 1 < IH) convert_row(smem, b, qg0, p0 - 1, gin);
            cur_strip = strip;
        }
#pragma unroll
        for (int rr = 0; rr < 4; rr++)
            if (p0 + rr < IH) convert_row(smem, b, qg0, p0 + rr, gin);
        __syncthreads();

        // ---- compute: this warp's row pw, 16px x 32co ----
        const int pw = p0 + warp_r;
        float c[4][4];
#pragma unroll
        for (int i = 0; i < 4; i++)
#pragma unroll
            for (int j = 0; j < 4; j++) c[i][j] = 0.f;

#pragma unroll
        for (int di = 0; di < 3; di++) {
            const int rp = pw - di;
            if (rp < 0 || rp >= IH) continue;
            const uint32_t aBase = sb + SM_A + (uint32_t)(rp & 7) * A_SLOT;
#pragma unroll
            for (int dj = 0; dj < 3; dj++) {
                const int tap = di * 3 + dj;
                const int rowi = warp_m * 16 + lm + 2 - dj;
                const uint32_t arow = (uint32_t)rowi * 128;
                const uint32_t am = (uint32_t)(rowi & 7) << 4;
                const uint32_t bb = sb + SM_B + (uint32_t)tap * B_TAP;
#pragma unroll
                for (int s = 0; s < 4; s++) {
                    const uint32_t kx = (uint32_t)s * 32 + kcl;
                    uint32_t B0[4], B1[4], A[4];
                    ldm4(B0, bb + brow0 + (kx ^ bm0));
                    ldm4(B1, bb + brow1 + (kx ^ bm1));
                    ldm4(A, aBase + arow + (kx ^ am));
                    mma16816(c[0], A, B0[0], B0[2]);
                    mma16816(c[1], A, B0[1], B0[3]);
                    mma16816(c[2], A, B1[0], B1[2]);
                    mma16816(c[3], A, B1[1], B1[3]);
                }
            }
        }

        // ---- store this warp's row ----
        const int p = pw;
        if (p < OH) {
            const int q = qg0 + warp_m * 16 + (lane >> 2);
            float* orow = gout + (((size_t)b * OH + p) * OW + q) * NCH;
#pragma unroll
            for (int nt = 0; nt < 4; nt++) {
                const int co = warp_n * 32 + nt * 8 + (lane & 3) * 2;
                *(float2*)(orow + co) = make_float2(c[nt][0], c[nt][1]);
                *(float2*)(orow + 8 * NCH + co) = make_float2(c[nt][2], c[nt][3]);
            }
        }
    }

    // ================= tail units: q in {256,257}, 64 px per unit ============
    if (blockIdx.x < NTAIL) {
        const int t = blockIdx.x;
        const int g0 = t * 64;

        float ct[4][4];
#pragma unroll
        for (int i = 0; i < 4; i++)
#pragma unroll
            for (int j = 0; j < 4; j++) ct[i][j] = 0.f;

        const int rowi = warp_m * 16 + lm;
        const uint32_t arow = (uint32_t)rowi * 128;
        const uint32_t am = (uint32_t)(rowi & 7) << 4;

        for (int tap = 0; tap < 9; tap++) {
            const int di = tap / 3, dj = tap % 3;
            __syncthreads();   // prev tap's mma reads done
            // im2col gather into A slot 0
            for (int idx = tid; idx < 64 * 16; idx += NTHR) {
                int m = idx >> 4, c4 = idx & 15;
                int g = g0 + m;
                int bb_ = g / (OH * 2);
                int rem = g - bb_ * (OH * 2);
                int p = rem >> 1;
                int qq = 256 + (rem & 1);
                int r = p - di, cc = qq - dj;
                float4 v = make_float4(0.f, 0.f, 0.f, 0.f);
                if (g < NTPX && r >= 0 && r < IH && cc < IW)
                    v = __ldg((const float4*)(gin +
                        ((((size_t)bb_ * IH + r) * IW + cc) * NCH) + c4 * 4));
                __half2 h01 = make_half2(__float2half_rn(v.x), __float2half_rn(v.y));
                __half2 h23 = make_half2(__float2half_rn(v.z), __float2half_rn(v.w));
                uint32_t off = (uint32_t)m * 128 + (uint32_t)c4 * 8;
                uint32_t sw = off ^ ((off >> 3) & 0x70);
                *(uint2*)(smem + SM_A + sw) = make_uint2(*(uint32_t*)&h01, *(uint32_t*)&h23);
            }
            __syncthreads();

            if (warp_r == 0) {
                const uint32_t bb = sb + SM_B + (uint32_t)tap * B_TAP;
#pragma unroll
                for (int s = 0; s < 4; s++) {
                    const uint32_t kx = (uint32_t)s * 32 + kcl;
                    uint32_t B0[4], B1[4], A[4];
                    ldm4(B0, bb + brow0 + (kx ^ bm0));
                    ldm4(B1, bb + brow1 + (kx ^ bm1));
                    ldm4(A, sb + SM_A + arow + (kx ^ am));
                    mma16816(ct[0], A, B0[0], B0[2]);
                    mma16816(ct[1], A, B0[1], B0[3]);
                    mma16816(ct[2], A, B1[0], B1[2]);
                    mma16816(ct[3], A, B1[1], B1[3]);
                }
            }
        }

        // store tail (warps with warp_r==0 own the 64x64 tile)
        if (warp_r == 0) {
            const int m0 = warp_m * 16 + (lane >> 2);
#pragma unroll
            for (int half = 0; half < 2; half++) {
                const int g = g0 + m0 + half * 8;
                if (g < NTPX) {
                    const int bb_ = g / (OH * 2);
                    const int rem = g - bb_ * (OH * 2);
                    const int p = rem >> 1;
                    const int qq = 256 + (rem & 1);
                    float* orow = gout + (((size_t)bb_ * OH + p) * OW + qq) * NCH;
#pragma unroll
                    for (int nt = 0; nt < 4; nt++) {
                        const int co = warp_n * 32 + nt * 8 + (lane & 3) * 2;
                        *(float2*)(orow + co) =
                            make_float2(ct[nt][half * 2], ct[nt][half * 2 + 1]);
                    }
                }
            }
        }
    }
}

extern "C" void kernel_launch(void* const* d_in, const int* in_sizes, int n_in,
                              void* d_out, int out_size)
{
    const float* gin = (const float*)d_in[0]; // [8,256,256,64]
    const float* gw  = (const float*)d_in[1]; // [64,64,3,3]
    float* gout = (float*)d_out;              // [8,258,258,64]

    cudaFuncSetAttribute(tconv_mma_kernel,
                         cudaFuncAttributeMaxDynamicSharedMemorySize, SM_TOTAL);
    tconv_mma_kernel<<<NCTA, NTHR, SM_TOTAL>>>(gin, gw, gout);
}